// round 13
// baseline (speedup 1.0000x reference)
#include <cuda_runtime.h>
#include <cstdint>
#include <cstddef>

// Legacy-path (mma.sync m16n8k8.tf32) fused NeuralCTLSTM, v11:
// Crossbar-optimal warp tile m48 x n16 x 7 gates (M=3: bytes/HMMA 164->122).
// 8 warps/CTA, warp-private 2-stage cp.async A rings (48x36 padded rows),
// W (7x16x256 = 112KB) resident pre-permuted, bias in smem.
// Epilogue operands warmed via prefetch.global.L2 at chunk 5 (no smem left
// for C staging at m48). 65536 = 1366 blocks of 48 with an overlapped tail
// (identical double-writes, deterministic). Grid (16, 9) = 144 CTAs.

#define NG 7
#define HH 256
#define BK 32
#define NCHUNK 8
#define THREADS 256
#define GYS 9
#define STREAMS (8 * GYS)                   // 72 warp-streams per o-block
#define MT 3
#define BROWS 48                            // rows per block (m48)

#define OFF_BIAS 0                          // 112 floats + pad = 512B
#define OFF_W 512
#define W_BYTES (NG * NCHUNK * 2 * 2 * 512) // 224 frag-units x 512B = 114688
#define A_P 36                              // padded A row stride (floats)
#define A_STAGE_B (BROWS * A_P * 4)         // 6912
#define A_WARP_B (2 * A_STAGE_B)            // 13824
#define OFF_A (OFF_W + W_BYTES)             // 115200
#define SMEM_BYTES (OFF_A + 8 * A_WARP_B)   // 225792

__device__ __forceinline__ uint32_t f2tf32(float f) {
    uint32_t u;
    asm("cvt.rna.tf32.f32 %0, %1;" : "=r"(u) : "f"(f));
    return u;
}

__device__ __forceinline__ void mma_tf32(float* d, const uint32_t* a,
                                         uint32_t b0, uint32_t b1) {
    asm volatile(
        "mma.sync.aligned.m16n8k8.row.col.f32.tf32.tf32.f32 "
        "{%0,%1,%2,%3}, {%4,%5,%6,%7}, {%8,%9}, {%0,%1,%2,%3};\n"
        : "+f"(d[0]), "+f"(d[1]), "+f"(d[2]), "+f"(d[3])
        : "r"(a[0]), "r"(a[1]), "r"(a[2]), "r"(a[3]), "r"(b0), "r"(b1));
}

__device__ __forceinline__ void cp_async16(uint32_t dst, const void* src) {
    asm volatile("cp.async.cg.shared.global [%0], [%1], 16;\n"
                 :: "r"(dst), "l"(src) : "memory");
}

__device__ __forceinline__ void prefetch_l2(const void* p) {
    asm volatile("prefetch.global.L2 [%0];" :: "l"(p));
}

__device__ __forceinline__ float tanh_fast(float x) {
    float y;
    asm("tanh.approx.f32 %0, %1;" : "=f"(y) : "f"(x));
    return y;
}
__device__ __forceinline__ float sigm(float x) {       // 0.5*tanh(x/2)+0.5
    return fmaf(tanh_fast(0.5f * x), 0.5f, 0.5f);
}

extern "C" __global__ void __launch_bounds__(THREADS, 1)
nctlstm_v11_kernel(const float* __restrict__ inter_times,
                   const float* __restrict__ h_ti,
                   const float* __restrict__ c_ti,
                   const float* __restrict__ cbar,
                   const float* __restrict__ W,
                   const float* __restrict__ bias,
                   float* __restrict__ out,
                   int Btot)
{
    extern __shared__ char smem[];
    const uint32_t sb = (uint32_t)__cvta_generic_to_shared(smem);

    const int tid  = threadIdx.x;
    const int warp = tid >> 5;       // 0..7
    const int lane = tid & 31;
    const int grp  = lane >> 2;      // 0..7
    const int tig  = lane & 3;       // 0..3

    const int o0 = blockIdx.x * 16;
    const int stream = blockIdx.y * 8 + warp;    // 0..71
    const int nblk = (Btot + BROWS - 1) / BROWS; // 1366

    const float* bias_s = reinterpret_cast<const float*>(smem + OFF_BIAS);
    const uint4* wperm = reinterpret_cast<const uint4*>(smem + OFF_W);
    uint4* wperm_w = reinterpret_cast<uint4*>(smem + OFF_W);
    const uint32_t warpA = sb + OFF_A + (uint32_t)warp * A_WARP_B;
    const float*  warpAf = reinterpret_cast<const float*>(smem + OFF_A + warp * A_WARP_B);

    auto blk_start = [&](int i) { return min(BROWS * i, Btot - BROWS); };

    // ---- warp-private A chunk loader: 48 rows x 32 cols, 12 cp.async/lane --
    auto load_chunk = [&](int rstart, int ch, int s) {
        const uint32_t ab = warpA + (uint32_t)s * A_STAGE_B;
        const float* src = h_ti + (size_t)rstart * HH + ch * BK;
#pragma unroll
        for (int i = 0; i < 12; i++) {
            const int idx = lane + i * 32;        // 0..383
            const int r = idx >> 3, c4 = idx & 7;
            cp_async16(ab + (uint32_t)(r * (A_P * 4) + c4 * 16),
                       src + (size_t)r * HH + c4 * 4);
        }
        asm volatile("cp.async.commit_group;\n" ::: "memory");
    };

    // prologue: first two chunks of first block in flight during W permute
    const int i0 = stream;
    const int rs0 = blk_start(i0);
    load_chunk(rs0, 0, 0);
    load_chunk(rs0, 1, 1);

    // ---- one-time W permute (224 units, 8 warps cooperate) ----
    for (int u = warp; u < NG * NCHUNK * 2 * 2; u += 8) {
        const int nh = u & 1, p = (u >> 1) & 1, ch = (u >> 2) & 7, g = u >> 5;
        const int o = o0 + nh * 8 + grp;
        const int k = ch * 32 + p * 16 + tig;
        const float* ws = W + ((size_t)g * HH + o) * HH + k;
        uint4 v;
        v.x = f2tf32(ws[0]);
        v.y = f2tf32(ws[4]);
        v.z = f2tf32(ws[8]);
        v.w = f2tf32(ws[12]);
        wperm_w[u * 32 + lane] = v;
    }

    // bias -> smem (112 floats)
    if (tid < NG * 16) {
        float* bw = reinterpret_cast<float*>(smem + OFF_BIAS);
        bw[tid] = bias[(size_t)(tid >> 4) * HH + o0 + (tid & 15)];
    }

    __syncthreads();   // W permute + bias visible; only block barrier

    const size_t BHtot = (size_t)Btot * HH;
    int s_cons = 0;

    for (int i = i0; i < nblk; i += STREAMS) {
        const int rstart = blk_start(i);

        float acc[NG][2][MT][4];         // [g][nh][mt][frag]
#pragma unroll
        for (int g = 0; g < NG; g++)
#pragma unroll
            for (int nh = 0; nh < 2; nh++) {
                const float2 bb = *reinterpret_cast<const float2*>(
                    bias_s + g * 16 + nh * 8 + 2 * tig);
#pragma unroll
                for (int mt = 0; mt < MT; mt++) {
                    acc[g][nh][mt][0] = bb.x; acc[g][nh][mt][1] = bb.y;
                    acc[g][nh][mt][2] = bb.x; acc[g][nh][mt][3] = bb.y;
                }
            }

#pragma unroll 1
        for (int ch = 0; ch < NCHUNK; ch++) {
            asm volatile("cp.async.wait_group 1;\n" ::: "memory");

            const float* hs = warpAf + s_cons * (A_STAGE_B / 4);

            // warm epilogue operands ~2.5 chunks ahead of use
            if (ch == 5) {
#pragma unroll
                for (int j = 0; j < 2; j++) {
                    const int rr = lane + j * 32;
                    if (rr < BROWS) {
                        prefetch_l2(c_ti + (size_t)(rstart + rr) * HH + o0);
                        prefetch_l2(cbar + (size_t)(rstart + rr) * HH + o0);
                    }
                }
                if (lane < 2) prefetch_l2(inter_times + rstart + lane * 32);
            }

#pragma unroll
            for (int p = 0; p < 2; p++) {
                // A fragments for this k16 half (24 regs)
                uint32_t a[2][MT][4];    // [q][mt][frag]
#pragma unroll
                for (int q = 0; q < 2; q++) {
                    const int k0 = (2 * p + q) * 8;
#pragma unroll
                    for (int mt = 0; mt < MT; mt++) {
                        const int r = mt * 16 + grp;
                        a[q][mt][0] = __float_as_uint(hs[r * A_P + k0 + tig]);
                        a[q][mt][1] = __float_as_uint(hs[(r + 8) * A_P + k0 + tig]);
                        a[q][mt][2] = __float_as_uint(hs[r * A_P + k0 + tig + 4]);
                        a[q][mt][3] = __float_as_uint(hs[(r + 8) * A_P + k0 + tig + 4]);
                    }
                }

                if (p == 1) {
                    // all LDS from stage s_cons issued: safe to overwrite.
                    int c2 = ch + 2, i2 = i;
                    if (c2 >= NCHUNK) { c2 -= NCHUNK; i2 += STREAMS; }
                    if (i2 < nblk) load_chunk(blk_start(i2), c2, s_cons);
                    else asm volatile("cp.async.commit_group;\n" ::: "memory");
                }

#pragma unroll
                for (int g = 0; g < NG; g++) {
#pragma unroll
                    for (int nh = 0; nh < 2; nh++) {
                        const uint4 wf =
                            wperm[((((g * 8 + ch) * 2 + p) * 2) + nh) * 32 + lane];
#pragma unroll
                        for (int mt = 0; mt < MT; mt++) {
                            mma_tf32(acc[g][nh][mt], a[0][mt], wf.x, wf.y);
                            mma_tf32(acc[g][nh][mt], a[1][mt], wf.z, wf.w);
                        }
                    }
                }
            }
            s_cons ^= 1;
        }

        // ---- fused epilogue: operands L2-warm from chunk-5 prefetch ----
#pragma unroll
        for (int mt = 0; mt < MT; mt++) {
#pragma unroll
            for (int rs = 0; rs < 2; rs++) {
                const int row = mt * 16 + grp + rs * 8;       // 0..47
                const int b = rstart + row;
                const float dt = __ldg(inter_times + b);
#pragma unroll
                for (int nh = 0; nh < 2; nh++) {
                    const int col = nh * 8 + 2 * tig;
                    const size_t base = (size_t)b * HH + o0 + col;
                    const float2 cv = __ldcs(reinterpret_cast<const float2*>(c_ti + base));
                    const float2 cb = __ldcs(reinterpret_cast<const float2*>(cbar + base));

                    float2 r_o, r_h, r_c, r_cb, r_d;
#pragma unroll
                    for (int j = 0; j < 2; j++) {
                        const int ai = rs * 2 + j;
                        const float gi  = acc[0][nh][mt][ai];
                        const float gf  = acc[1][nh][mt][ai];
                        const float go  = acc[2][nh][mt][ai];
                        const float gib = acc[3][nh][mt][ai];
                        const float gfb = acc[4][nh][mt][ai];
                        const float gz  = acc[5][nh][mt][ai];
                        const float gd  = acc[6][nh][mt][ai];

                        const float i_g  = sigm(gi);
                        const float f_g  = sigm(gf);
                        const float o_g  = sigm(go);
                        const float ib_g = sigm(gib);
                        const float fb_g = sigm(gfb);
                        const float z    = tanh_fast(gz);
                        const float decay = fmaxf(gd, 0.0f)
                                          + __logf(1.0f + __expf(-fabsf(gd)));

                        const float ct  = (j == 0) ? cv.x : cv.y;
                        const float cbv = (j == 0) ? cb.x : cb.y;

                        const float e       = __expf(-decay * dt);
                        const float c_after = cbv + (ct - cbv) * e;
                        const float c_new   = f_g * c_after + i_g * z;
                        const float cb_new  = fb_g * cbv + ib_g * z;
                        const float h_new   = o_g * tanh_fast(c_after);

                        if (j == 0) { r_o.x = o_g; r_h.x = h_new; r_c.x = c_new; r_cb.x = cb_new; r_d.x = decay; }
                        else        { r_o.y = o_g; r_h.y = h_new; r_c.y = c_new; r_cb.y = cb_new; r_d.y = decay; }
                    }
                    __stcs(reinterpret_cast<float2*>(out + 0 * BHtot + base), r_o);
                    __stcs(reinterpret_cast<float2*>(out + 1 * BHtot + base), r_h);
                    __stcs(reinterpret_cast<float2*>(out + 2 * BHtot + base), r_c);
                    __stcs(reinterpret_cast<float2*>(out + 3 * BHtot + base), r_cb);
                    __stcs(reinterpret_cast<float2*>(out + 4 * BHtot + base), r_d);
                }
            }
        }
    }
}

extern "C" void kernel_launch(void* const* d_in, const int* in_sizes, int n_in,
                              void* d_out, int out_size)
{
    const float* inter_times = (const float*)d_in[0];
    const float* h_ti        = (const float*)d_in[1];
    const float* c_ti        = (const float*)d_in[2];
    const float* cbar        = (const float*)d_in[3];
    const float* W           = (const float*)d_in[4];
    const float* bias        = (const float*)d_in[5];
    const int B = in_sizes[0];

    cudaFuncSetAttribute(nctlstm_v11_kernel,
                         cudaFuncAttributeMaxDynamicSharedMemorySize, SMEM_BYTES);

    dim3 grid(16, GYS);   // 144 CTAs = one wave; one 16-col o-block per CTA
    nctlstm_v11_kernel<<<grid, THREADS, SMEM_BYTES>>>(
        inter_times, h_ti, c_ti, cbar, W, bias, (float*)d_out, B);
}

// round 14
// speedup vs baseline: 2.0166x; 2.0166x over previous
#include <cuda_runtime.h>
#include <cuda_fp16.h>
#include <cstdint>
#include <cstddef>

// Legacy-path fused NeuralCTLSTM, v12: fp16 operands (same 11-bit mantissa
// as tf32 -> same accuracy), mma.m16n8k16.f32.f16.f16.f32 at 2x tf32 rate,
// half the smem bytes. Structure = proven v9: 8 warps, m32 x n16 x 7 gates,
// warp-private 2-stage cp.async rings, W resident pre-permuted (56KB),
// epilogue operand staging. Pre-pass kernel converts h_ti to fp16 in a
// __device__ scratch buffer. Grid (16, 9) = 144 CTAs = one wave.

#define NG 7
#define HH 256
#define BK 32
#define NCHUNK 8
#define THREADS 256
#define GYS 9
#define STREAMS (8 * GYS)                   // 72 warp-streams per o-block

#define OFF_BIAS 0                          // 112 floats + pad = 512B
#define OFF_W 512
#define W_BYTES (NG * NCHUNK * 2 * 512)     // 112 frag-units x 512B = 57344
#define A_P_B 80                            // A stage row stride (bytes)
#define A_STAGE_B (32 * A_P_B)              // 2560
#define A_WARP_B (2 * A_STAGE_B)            // 5120
#define OFF_A (OFF_W + W_BYTES)             // 57856
#define C_STRIDE_F 20                       // 80B row stride (16B-aligned)
#define C_ARR_B (32 * C_STRIDE_F * 4)       // 2560
#define C_WARP_B (2 * C_ARR_B + 128)        // c, cbar, dt = 5248
#define OFF_C (OFF_A + 8 * A_WARP_B)        // 98816
#define SMEM_BYTES (OFF_C + 8 * C_WARP_B)   // 140800

// fp16 copy of h_ti (B x H = 16.78M halfs = 32MB scratch)
__device__ __align__(16) __half2 g_h16[(65536 * 256) / 2];

__device__ __forceinline__ uint32_t pack_h2(float a, float b) {
    __half2 h = __floats2half2_rn(a, b);
    return *reinterpret_cast<uint32_t*>(&h);
}

__device__ __forceinline__ void mma_f16(float* d, const uint32_t* a,
                                        uint32_t b0, uint32_t b1) {
    asm volatile(
        "mma.sync.aligned.m16n8k16.row.col.f32.f16.f16.f32 "
        "{%0,%1,%2,%3}, {%4,%5,%6,%7}, {%8,%9}, {%0,%1,%2,%3};\n"
        : "+f"(d[0]), "+f"(d[1]), "+f"(d[2]), "+f"(d[3])
        : "r"(a[0]), "r"(a[1]), "r"(a[2]), "r"(a[3]), "r"(b0), "r"(b1));
}

__device__ __forceinline__ void cp_async16(uint32_t dst, const void* src) {
    asm volatile("cp.async.cg.shared.global [%0], [%1], 16;\n"
                 :: "r"(dst), "l"(src) : "memory");
}

__device__ __forceinline__ float tanh_fast(float x) {
    float y;
    asm("tanh.approx.f32 %0, %1;" : "=f"(y) : "f"(x));
    return y;
}
__device__ __forceinline__ float sigm(float x) {       // 0.5*tanh(x/2)+0.5
    return fmaf(tanh_fast(0.5f * x), 0.5f, 0.5f);
}

// ---- pre-pass: h_ti fp32 -> fp16 scratch (8 elems/thread) ----
extern "C" __global__ void __launch_bounds__(256, 1)
nctlstm_cvt_kernel(const float* __restrict__ src, int n8)
{
    const int i = blockIdx.x * 256 + threadIdx.x;
    if (i < n8) {
        const float4 f0 = reinterpret_cast<const float4*>(src)[2 * i];
        const float4 f1 = reinterpret_cast<const float4*>(src)[2 * i + 1];
        g_h16[4 * i + 0] = __floats2half2_rn(f0.x, f0.y);
        g_h16[4 * i + 1] = __floats2half2_rn(f0.z, f0.w);
        g_h16[4 * i + 2] = __floats2half2_rn(f1.x, f1.y);
        g_h16[4 * i + 3] = __floats2half2_rn(f1.z, f1.w);
    }
}

extern "C" __global__ void __launch_bounds__(THREADS, 1)
nctlstm_v12_kernel(const float* __restrict__ inter_times,
                   const float* __restrict__ c_ti,
                   const float* __restrict__ cbar,
                   const float* __restrict__ W,
                   const float* __restrict__ bias,
                   float* __restrict__ out,
                   int Btot)
{
    extern __shared__ char smem[];
    const uint32_t sb = (uint32_t)__cvta_generic_to_shared(smem);

    const int tid  = threadIdx.x;
    const int warp = tid >> 5;       // 0..7
    const int lane = tid & 31;
    const int grp  = lane >> 2;      // 0..7
    const int tig  = lane & 3;       // 0..3

    const int o0 = blockIdx.x * 16;
    const int stream = blockIdx.y * 8 + warp;    // 0..71
    const int nblk = Btot >> 5;                  // 2048 32-row blocks

    const __half* h16 = reinterpret_cast<const __half*>(g_h16);

    const float* bias_s = reinterpret_cast<const float*>(smem + OFF_BIAS);
    const uint4* wperm = reinterpret_cast<const uint4*>(smem + OFF_W);
    uint4* wperm_w = reinterpret_cast<uint4*>(smem + OFF_W);
    const uint32_t warpA = sb + OFF_A + (uint32_t)warp * A_WARP_B;
    const char*   warpAc = smem + OFF_A + warp * A_WARP_B;
    const uint32_t warpC = sb + OFF_C + (uint32_t)warp * C_WARP_B;
    const float*  c_s  = reinterpret_cast<const float*>(smem + OFF_C + warp * C_WARP_B);
    const float*  cb_s = c_s + (C_ARR_B / 4);
    const float*  dt_s = cb_s + (C_ARR_B / 4);

    // ---- warp-private A chunk loader: 32 rows x 32 halfs, 4 cp.async/lane --
    auto load_chunk = [&](int rb, int ch, int s) {
        const uint32_t ab = warpA + (uint32_t)s * A_STAGE_B;
        const __half* src = h16 + ((size_t)rb << 5) * HH + ch * BK;
#pragma unroll
        for (int i = 0; i < 4; i++) {
            const int idx = lane + i * 32;        // 0..127
            const int r = idx >> 2, g16 = idx & 3;
            cp_async16(ab + (uint32_t)(r * A_P_B + g16 * 16),
                       src + (size_t)r * HH + g16 * 8);
        }
        asm volatile("cp.async.commit_group;\n" ::: "memory");
    };

    // ---- epilogue-operand stager (NO commit; joins caller's group) ----
    auto load_cblock = [&](int rb) {
        const float* csrc  = c_ti + ((size_t)rb << 5) * HH + o0;
        const float* cbsrc = cbar + ((size_t)rb << 5) * HH + o0;
#pragma unroll
        for (int i = 0; i < 4; i++) {
            const int idx = lane + i * 32;        // 0..127
            const int r = idx >> 2, cg = idx & 3;
            cp_async16(warpC + (uint32_t)(r * (C_STRIDE_F * 4) + cg * 16),
                       csrc + (size_t)r * HH + cg * 4);
            cp_async16(warpC + (uint32_t)(C_ARR_B + r * (C_STRIDE_F * 4) + cg * 16),
                       cbsrc + (size_t)r * HH + cg * 4);
        }
        if (lane < 8)
            cp_async16(warpC + (uint32_t)(2 * C_ARR_B + lane * 16),
                       inter_times + (rb << 5) + lane * 4);
    };

    // prologue: first two chunks of first block in flight during W permute
    const int rb0 = stream;
    load_chunk(rb0, 0, 0);
    load_chunk(rb0, 1, 1);

    // ---- one-time W permute to fp16 k16-frag order (112 units) ----
    // unit u = (g*8 + ch)*2 + nh; lane (grp,tig) holds for o = o0+nh*8+grp:
    //  v.x = {W[o][32ch+2tig],   +1}   (ks0 b0)
    //  v.y = {W[o][32ch+8+2tig], +1}   (ks0 b1)
    //  v.z = {W[o][32ch+16+2tig],+1}   (ks1 b0)
    //  v.w = {W[o][32ch+24+2tig],+1}   (ks1 b1)
    for (int u = warp; u < NG * NCHUNK * 2; u += 8) {
        const int nh = u & 1, ch = (u >> 1) & 7, g = u >> 4;
        const int o = o0 + nh * 8 + grp;
        const float* ws = W + ((size_t)g * HH + o) * HH + ch * 32 + 2 * tig;
        uint4 v;
        v.x = pack_h2(ws[0],  ws[1]);
        v.y = pack_h2(ws[8],  ws[9]);
        v.z = pack_h2(ws[16], ws[17]);
        v.w = pack_h2(ws[24], ws[25]);
        wperm_w[u * 32 + lane] = v;
    }

    // bias -> smem (112 floats, fp32)
    if (tid < NG * 16) {
        float* bw = reinterpret_cast<float*>(smem + OFF_BIAS);
        bw[tid] = bias[(size_t)(tid >> 4) * HH + o0 + (tid & 15)];
    }

    __syncthreads();   // W permute + bias visible; only block barrier

    const size_t BHtot = (size_t)Btot * HH;
    int s_cons = 0;

    for (int rb = rb0; rb < nblk; rb += STREAMS) {
        float acc[NG][2][2][4];          // [g][nh][mt][frag]
#pragma unroll
        for (int g = 0; g < NG; g++)
#pragma unroll
            for (int nh = 0; nh < 2; nh++) {
                const float2 bb = *reinterpret_cast<const float2*>(
                    bias_s + g * 16 + nh * 8 + 2 * tig);
#pragma unroll
                for (int mt = 0; mt < 2; mt++) {
                    acc[g][nh][mt][0] = bb.x; acc[g][nh][mt][1] = bb.y;
                    acc[g][nh][mt][2] = bb.x; acc[g][nh][mt][3] = bb.y;
                }
            }

#pragma unroll 1
        for (int ch = 0; ch < NCHUNK; ch++) {
            asm volatile("cp.async.wait_group 1;\n" ::: "memory");

            const char* hs = warpAc + s_cons * A_STAGE_B;

            // A fragments for both k16-steps (16 regs); LDS.32 each holds
            // {A[r][kb+2tig], A[r][kb+2tig+1]} as packed half2.
            uint32_t a[2][2][4];         // [ks][mt][frag]
#pragma unroll
            for (int ks = 0; ks < 2; ks++) {
#pragma unroll
                for (int mt = 0; mt < 2; mt++) {
                    const int r = mt * 16 + grp;
                    const char* rp0 = hs + r * A_P_B + ks * 32 + tig * 4;
                    const char* rp1 = hs + (r + 8) * A_P_B + ks * 32 + tig * 4;
                    a[ks][mt][0] = *reinterpret_cast<const uint32_t*>(rp0);
                    a[ks][mt][1] = *reinterpret_cast<const uint32_t*>(rp1);
                    a[ks][mt][2] = *reinterpret_cast<const uint32_t*>(rp0 + 16);
                    a[ks][mt][3] = *reinterpret_cast<const uint32_t*>(rp1 + 16);
                }
            }

            // all LDS from stage s_cons issued: safe to overwrite it.
            // chunk 0 also stages this block's epilogue operands (same group).
            {
                if (ch == 0) load_cblock(rb);
                int c2 = ch + 2, r2 = rb;
                if (c2 >= NCHUNK) { c2 -= NCHUNK; r2 += STREAMS; }
                if (r2 < nblk) load_chunk(r2, c2, s_cons);
                else           asm volatile("cp.async.commit_group;\n" ::: "memory");
            }
            s_cons ^= 1;

            // 14 LDS.128 (W frags) + 56 k16-MMAs
#pragma unroll
            for (int g = 0; g < NG; g++) {
#pragma unroll
                for (int nh = 0; nh < 2; nh++) {
                    const uint4 wf = wperm[(((g * 8 + ch) * 2) + nh) * 32 + lane];
                    mma_f16(acc[g][nh][0], a[0][0], wf.x, wf.y);
                    mma_f16(acc[g][nh][1], a[0][1], wf.x, wf.y);
                    mma_f16(acc[g][nh][0], a[1][0], wf.z, wf.w);
                    mma_f16(acc[g][nh][1], a[1][1], wf.z, wf.w);
                }
            }
        }

        // ---- fused epilogue: all operands in smem (staged in chunk 0) ----
#pragma unroll
        for (int mt = 0; mt < 2; mt++) {
#pragma unroll
            for (int rs = 0; rs < 2; rs++) {
                const int row = mt * 16 + grp + rs * 8;       // 0..31
                const int b = rb * 32 + row;
                const float dt = dt_s[row];
#pragma unroll
                for (int nh = 0; nh < 2; nh++) {
                    const int col = nh * 8 + 2 * tig;
                    const float2 cv = *reinterpret_cast<const float2*>(
                        c_s + row * C_STRIDE_F + col);
                    const float2 cb = *reinterpret_cast<const float2*>(
                        cb_s + row * C_STRIDE_F + col);
                    const size_t base = (size_t)b * HH + o0 + col;

                    float2 r_o, r_h, r_c, r_cb, r_d;
#pragma unroll
                    for (int j = 0; j < 2; j++) {
                        const int ai = rs * 2 + j;
                        const float gi  = acc[0][nh][mt][ai];
                        const float gf  = acc[1][nh][mt][ai];
                        const float go  = acc[2][nh][mt][ai];
                        const float gib = acc[3][nh][mt][ai];
                        const float gfb = acc[4][nh][mt][ai];
                        const float gz  = acc[5][nh][mt][ai];
                        const float gd  = acc[6][nh][mt][ai];

                        const float i_g  = sigm(gi);
                        const float f_g  = sigm(gf);
                        const float o_g  = sigm(go);
                        const float ib_g = sigm(gib);
                        const float fb_g = sigm(gfb);
                        const float z    = tanh_fast(gz);
                        const float decay = fmaxf(gd, 0.0f)
                                          + __logf(1.0f + __expf(-fabsf(gd)));

                        const float ct  = (j == 0) ? cv.x : cv.y;
                        const float cbv = (j == 0) ? cb.x : cb.y;

                        const float e       = __expf(-decay * dt);
                        const float c_after = cbv + (ct - cbv) * e;
                        const float c_new   = f_g * c_after + i_g * z;
                        const float cb_new  = fb_g * cbv + ib_g * z;
                        const float h_new   = o_g * tanh_fast(c_after);

                        if (j == 0) { r_o.x = o_g; r_h.x = h_new; r_c.x = c_new; r_cb.x = cb_new; r_d.x = decay; }
                        else        { r_o.y = o_g; r_h.y = h_new; r_c.y = c_new; r_cb.y = cb_new; r_d.y = decay; }
                    }
                    __stcs(reinterpret_cast<float2*>(out + 0 * BHtot + base), r_o);
                    __stcs(reinterpret_cast<float2*>(out + 1 * BHtot + base), r_h);
                    __stcs(reinterpret_cast<float2*>(out + 2 * BHtot + base), r_c);
                    __stcs(reinterpret_cast<float2*>(out + 3 * BHtot + base), r_cb);
                    __stcs(reinterpret_cast<float2*>(out + 4 * BHtot + base), r_d);
                }
            }
        }
    }
}

extern "C" void kernel_launch(void* const* d_in, const int* in_sizes, int n_in,
                              void* d_out, int out_size)
{
    const float* inter_times = (const float*)d_in[0];
    const float* h_ti        = (const float*)d_in[1];
    const float* c_ti        = (const float*)d_in[2];
    const float* cbar        = (const float*)d_in[3];
    const float* W           = (const float*)d_in[4];
    const float* bias        = (const float*)d_in[5];
    const int B = in_sizes[0];

    // pre-pass: h_ti -> fp16 scratch
    const int n8 = (B * HH) / 8;
    nctlstm_cvt_kernel<<<(n8 + 255) / 256, 256>>>(h_ti, n8);

    cudaFuncSetAttribute(nctlstm_v12_kernel,
                         cudaFuncAttributeMaxDynamicSharedMemorySize, SMEM_BYTES);

    dim3 grid(16, GYS);   // 144 CTAs = one wave; one 16-col o-block per CTA
    nctlstm_v12_kernel<<<grid, THREADS, SMEM_BYTES>>>(
        inter_times, c_ti, cbar, W, bias, (float*)d_out, B);
}

// round 15
// speedup vs baseline: 2.0968x; 1.0397x over previous
#include <cuda_runtime.h>
#include <cuda_fp16.h>
#include <cstdint>
#include <cstddef>

// Legacy-path fused NeuralCTLSTM, v13: fp16 operands + 12 warps/CTA
// (3 per SMSP). fp16 halves smem (W 56KB, A stages 2.5KB) so the 12-warp
// config that was smem-impossible at tf32 now fits: 181760B total.
// Structure = proven v12: m32 x n16 x 7 gates per warp, warp-private
// 2-stage cp.async rings, W resident pre-permuted, epilogue staging.
// Pre-pass converts h_ti to fp16 scratch. Grid (16, 9) = 144 CTAs.

#define NG 7
#define HH 256
#define BK 32
#define NCHUNK 8
#define THREADS 384
#define GYS 9
#define STREAMS (12 * GYS)                  // 108 warp-streams per o-block

#define OFF_BIAS 0                          // 112 floats + pad = 512B
#define OFF_W 512
#define W_BYTES (NG * NCHUNK * 2 * 512)     // 112 frag-units x 512B = 57344
#define A_P_B 80                            // A stage row stride (bytes)
#define A_STAGE_B (32 * A_P_B)              // 2560
#define A_WARP_B (2 * A_STAGE_B)            // 5120
#define OFF_A (OFF_W + W_BYTES)             // 57856
#define C_STRIDE_F 20                       // 80B row stride (16B-aligned)
#define C_ARR_B (32 * C_STRIDE_F * 4)       // 2560
#define C_WARP_B (2 * C_ARR_B + 128)        // c, cbar, dt = 5248
#define OFF_C (OFF_A + 12 * A_WARP_B)       // 119296
#define SMEM_BYTES (OFF_C + 12 * C_WARP_B)  // 182272

// fp16 copy of h_ti (B x H = 16.78M halfs = 32MB scratch)
__device__ __align__(16) __half2 g_h16[(65536 * 256) / 2];

__device__ __forceinline__ uint32_t pack_h2(float a, float b) {
    __half2 h = __floats2half2_rn(a, b);
    return *reinterpret_cast<uint32_t*>(&h);
}

__device__ __forceinline__ void mma_f16(float* d, const uint32_t* a,
                                        uint32_t b0, uint32_t b1) {
    asm volatile(
        "mma.sync.aligned.m16n8k16.row.col.f32.f16.f16.f32 "
        "{%0,%1,%2,%3}, {%4,%5,%6,%7}, {%8,%9}, {%0,%1,%2,%3};\n"
        : "+f"(d[0]), "+f"(d[1]), "+f"(d[2]), "+f"(d[3])
        : "r"(a[0]), "r"(a[1]), "r"(a[2]), "r"(a[3]), "r"(b0), "r"(b1));
}

__device__ __forceinline__ void cp_async16(uint32_t dst, const void* src) {
    asm volatile("cp.async.cg.shared.global [%0], [%1], 16;\n"
                 :: "r"(dst), "l"(src) : "memory");
}

__device__ __forceinline__ float tanh_fast(float x) {
    float y;
    asm("tanh.approx.f32 %0, %1;" : "=f"(y) : "f"(x));
    return y;
}
__device__ __forceinline__ float sigm(float x) {       // 0.5*tanh(x/2)+0.5
    return fmaf(tanh_fast(0.5f * x), 0.5f, 0.5f);
}

// ---- pre-pass: h_ti fp32 -> fp16 scratch (8 elems/thread) ----
extern "C" __global__ void __launch_bounds__(256, 1)
nctlstm_cvt_kernel(const float* __restrict__ src, int n8)
{
    const int i = blockIdx.x * 256 + threadIdx.x;
    if (i < n8) {
        const float4 f0 = reinterpret_cast<const float4*>(src)[2 * i];
        const float4 f1 = reinterpret_cast<const float4*>(src)[2 * i + 1];
        g_h16[4 * i + 0] = __floats2half2_rn(f0.x, f0.y);
        g_h16[4 * i + 1] = __floats2half2_rn(f0.z, f0.w);
        g_h16[4 * i + 2] = __floats2half2_rn(f1.x, f1.y);
        g_h16[4 * i + 3] = __floats2half2_rn(f1.z, f1.w);
    }
}

extern "C" __global__ void __launch_bounds__(THREADS, 1)
nctlstm_v13_kernel(const float* __restrict__ inter_times,
                   const float* __restrict__ c_ti,
                   const float* __restrict__ cbar,
                   const float* __restrict__ W,
                   const float* __restrict__ bias,
                   float* __restrict__ out,
                   int Btot)
{
    extern __shared__ char smem[];
    const uint32_t sb = (uint32_t)__cvta_generic_to_shared(smem);

    const int tid  = threadIdx.x;
    const int warp = tid >> 5;       // 0..11
    const int lane = tid & 31;
    const int grp  = lane >> 2;      // 0..7
    const int tig  = lane & 3;       // 0..3

    const int o0 = blockIdx.x * 16;
    const int stream = blockIdx.y * 12 + warp;   // 0..107
    const int nblk = Btot >> 5;                  // 2048 32-row blocks

    const __half* h16 = reinterpret_cast<const __half*>(g_h16);

    const float* bias_s = reinterpret_cast<const float*>(smem + OFF_BIAS);
    const uint4* wperm = reinterpret_cast<const uint4*>(smem + OFF_W);
    uint4* wperm_w = reinterpret_cast<uint4*>(smem + OFF_W);
    const uint32_t warpA = sb + OFF_A + (uint32_t)warp * A_WARP_B;
    const char*   warpAc = smem + OFF_A + warp * A_WARP_B;
    const uint32_t warpC = sb + OFF_C + (uint32_t)warp * C_WARP_B;
    const float*  c_s  = reinterpret_cast<const float*>(smem + OFF_C + warp * C_WARP_B);
    const float*  cb_s = c_s + (C_ARR_B / 4);
    const float*  dt_s = cb_s + (C_ARR_B / 4);

    // ---- warp-private A chunk loader: 32 rows x 32 halfs, 4 cp.async/lane --
    auto load_chunk = [&](int rb, int ch, int s) {
        const uint32_t ab = warpA + (uint32_t)s * A_STAGE_B;
        const __half* src = h16 + ((size_t)rb << 5) * HH + ch * BK;
#pragma unroll
        for (int i = 0; i < 4; i++) {
            const int idx = lane + i * 32;        // 0..127
            const int r = idx >> 2, g16 = idx & 3;
            cp_async16(ab + (uint32_t)(r * A_P_B + g16 * 16),
                       src + (size_t)r * HH + g16 * 8);
        }
        asm volatile("cp.async.commit_group;\n" ::: "memory");
    };

    // ---- epilogue-operand stager (NO commit; joins caller's group) ----
    auto load_cblock = [&](int rb) {
        const float* csrc  = c_ti + ((size_t)rb << 5) * HH + o0;
        const float* cbsrc = cbar + ((size_t)rb << 5) * HH + o0;
#pragma unroll
        for (int i = 0; i < 4; i++) {
            const int idx = lane + i * 32;        // 0..127
            const int r = idx >> 2, cg = idx & 3;
            cp_async16(warpC + (uint32_t)(r * (C_STRIDE_F * 4) + cg * 16),
                       csrc + (size_t)r * HH + cg * 4);
            cp_async16(warpC + (uint32_t)(C_ARR_B + r * (C_STRIDE_F * 4) + cg * 16),
                       cbsrc + (size_t)r * HH + cg * 4);
        }
        if (lane < 8)
            cp_async16(warpC + (uint32_t)(2 * C_ARR_B + lane * 16),
                       inter_times + (rb << 5) + lane * 4);
    };

    // prologue: first two chunks of first block in flight during W permute
    const int rb0 = stream;
    load_chunk(rb0, 0, 0);
    load_chunk(rb0, 1, 1);

    // ---- one-time W permute to fp16 k16-frag order (112 units) ----
    for (int u = warp; u < NG * NCHUNK * 2; u += 12) {
        const int nh = u & 1, ch = (u >> 1) & 7, g = u >> 4;
        const int o = o0 + nh * 8 + grp;
        const float* ws = W + ((size_t)g * HH + o) * HH + ch * 32 + 2 * tig;
        uint4 v;
        v.x = pack_h2(ws[0],  ws[1]);
        v.y = pack_h2(ws[8],  ws[9]);
        v.z = pack_h2(ws[16], ws[17]);
        v.w = pack_h2(ws[24], ws[25]);
        wperm_w[u * 32 + lane] = v;
    }

    // bias -> smem (112 floats, fp32)
    if (tid < NG * 16) {
        float* bw = reinterpret_cast<float*>(smem + OFF_BIAS);
        bw[tid] = bias[(size_t)(tid >> 4) * HH + o0 + (tid & 15)];
    }

    __syncthreads();   // W permute + bias visible; only block barrier

    const size_t BHtot = (size_t)Btot * HH;
    int s_cons = 0;

    for (int rb = rb0; rb < nblk; rb += STREAMS) {
        float acc[NG][2][2][4];          // [g][nh][mt][frag]
#pragma unroll
        for (int g = 0; g < NG; g++)
#pragma unroll
            for (int nh = 0; nh < 2; nh++) {
                const float2 bb = *reinterpret_cast<const float2*>(
                    bias_s + g * 16 + nh * 8 + 2 * tig);
#pragma unroll
                for (int mt = 0; mt < 2; mt++) {
                    acc[g][nh][mt][0] = bb.x; acc[g][nh][mt][1] = bb.y;
                    acc[g][nh][mt][2] = bb.x; acc[g][nh][mt][3] = bb.y;
                }
            }

#pragma unroll 1
        for (int ch = 0; ch < NCHUNK; ch++) {
            asm volatile("cp.async.wait_group 1;\n" ::: "memory");

            const char* hs = warpAc + s_cons * A_STAGE_B;

            // A fragments for both k16-steps (16 regs)
            uint32_t a[2][2][4];         // [ks][mt][frag]
#pragma unroll
            for (int ks = 0; ks < 2; ks++) {
#pragma unroll
                for (int mt = 0; mt < 2; mt++) {
                    const int r = mt * 16 + grp;
                    const char* rp0 = hs + r * A_P_B + ks * 32 + tig * 4;
                    const char* rp1 = hs + (r + 8) * A_P_B + ks * 32 + tig * 4;
                    a[ks][mt][0] = *reinterpret_cast<const uint32_t*>(rp0);
                    a[ks][mt][1] = *reinterpret_cast<const uint32_t*>(rp1);
                    a[ks][mt][2] = *reinterpret_cast<const uint32_t*>(rp0 + 16);
                    a[ks][mt][3] = *reinterpret_cast<const uint32_t*>(rp1 + 16);
                }
            }

            // all LDS from stage s_cons issued: safe to overwrite it.
            // chunk 0 also stages this block's epilogue operands (same group).
            {
                if (ch == 0) load_cblock(rb);
                int c2 = ch + 2, r2 = rb;
                if (c2 >= NCHUNK) { c2 -= NCHUNK; r2 += STREAMS; }
                if (r2 < nblk) load_chunk(r2, c2, s_cons);
                else           asm volatile("cp.async.commit_group;\n" ::: "memory");
            }
            s_cons ^= 1;

            // 14 LDS.128 (W frags) + 56 k16-MMAs
#pragma unroll
            for (int g = 0; g < NG; g++) {
#pragma unroll
                for (int nh = 0; nh < 2; nh++) {
                    const uint4 wf = wperm[(((g * 8 + ch) * 2) + nh) * 32 + lane];
                    mma_f16(acc[g][nh][0], a[0][0], wf.x, wf.y);
                    mma_f16(acc[g][nh][1], a[0][1], wf.x, wf.y);
                    mma_f16(acc[g][nh][0], a[1][0], wf.z, wf.w);
                    mma_f16(acc[g][nh][1], a[1][1], wf.z, wf.w);
                }
            }
        }

        // ---- fused epilogue: all operands in smem (staged in chunk 0) ----
#pragma unroll
        for (int mt = 0; mt < 2; mt++) {
#pragma unroll
            for (int rs = 0; rs < 2; rs++) {
                const int row = mt * 16 + grp + rs * 8;       // 0..31
                const int b = rb * 32 + row;
                const float dt = dt_s[row];
#pragma unroll
                for (int nh = 0; nh < 2; nh++) {
                    const int col = nh * 8 + 2 * tig;
                    const float2 cv = *reinterpret_cast<const float2*>(
                        c_s + row * C_STRIDE_F + col);
                    const float2 cb = *reinterpret_cast<const float2*>(
                        cb_s + row * C_STRIDE_F + col);
                    const size_t base = (size_t)b * HH + o0 + col;

                    float2 r_o, r_h, r_c, r_cb, r_d;
#pragma unroll
                    for (int j = 0; j < 2; j++) {
                        const int ai = rs * 2 + j;
                        const float gi  = acc[0][nh][mt][ai];
                        const float gf  = acc[1][nh][mt][ai];
                        const float go  = acc[2][nh][mt][ai];
                        const float gib = acc[3][nh][mt][ai];
                        const float gfb = acc[4][nh][mt][ai];
                        const float gz  = acc[5][nh][mt][ai];
                        const float gd  = acc[6][nh][mt][ai];

                        const float i_g  = sigm(gi);
                        const float f_g  = sigm(gf);
                        const float o_g  = sigm(go);
                        const float ib_g = sigm(gib);
                        const float fb_g = sigm(gfb);
                        const float z    = tanh_fast(gz);
                        const float decay = fmaxf(gd, 0.0f)
                                          + __logf(1.0f + __expf(-fabsf(gd)));

                        const float ct  = (j == 0) ? cv.x : cv.y;
                        const float cbv = (j == 0) ? cb.x : cb.y;

                        const float e       = __expf(-decay * dt);
                        const float c_after = cbv + (ct - cbv) * e;
                        const float c_new   = f_g * c_after + i_g * z;
                        const float cb_new  = fb_g * cbv + ib_g * z;
                        const float h_new   = o_g * tanh_fast(c_after);

                        if (j == 0) { r_o.x = o_g; r_h.x = h_new; r_c.x = c_new; r_cb.x = cb_new; r_d.x = decay; }
                        else        { r_o.y = o_g; r_h.y = h_new; r_c.y = c_new; r_cb.y = cb_new; r_d.y = decay; }
                    }
                    __stcs(reinterpret_cast<float2*>(out + 0 * BHtot + base), r_o);
                    __stcs(reinterpret_cast<float2*>(out + 1 * BHtot + base), r_h);
                    __stcs(reinterpret_cast<float2*>(out + 2 * BHtot + base), r_c);
                    __stcs(reinterpret_cast<float2*>(out + 3 * BHtot + base), r_cb);
                    __stcs(reinterpret_cast<float2*>(out + 4 * BHtot + base), r_d);
                }
            }
        }
    }
}

extern "C" void kernel_launch(void* const* d_in, const int* in_sizes, int n_in,
                              void* d_out, int out_size)
{
    const float* inter_times = (const float*)d_in[0];
    const float* h_ti        = (const float*)d_in[1];
    const float* c_ti        = (const float*)d_in[2];
    const float* cbar        = (const float*)d_in[3];
    const float* W           = (const float*)d_in[4];
    const float* bias        = (const float*)d_in[5];
    const int B = in_sizes[0];

    // pre-pass: h_ti -> fp16 scratch
    const int n8 = (B * HH) / 8;
    nctlstm_cvt_kernel<<<(n8 + 255) / 256, 256>>>(h_ti, n8);

    cudaFuncSetAttribute(nctlstm_v13_kernel,
                         cudaFuncAttributeMaxDynamicSharedMemorySize, SMEM_BYTES);

    dim3 grid(16, GYS);   // 144 CTAs = one wave; one 16-col o-block per CTA
    nctlstm_v13_kernel<<<grid, THREADS, SMEM_BYTES>>>(
        inter_times, c_ti, cbar, W, bias, (float*)d_out, B);
}

// round 16
// speedup vs baseline: 2.1525x; 1.0266x over previous
#include <cuda_runtime.h>
#include <cuda_fp16.h>
#include <cstdint>
#include <cstddef>

// Legacy-path fused NeuralCTLSTM, v14: v13 (fp16 operands, 12 warps, m32 x
// n16 x 7g, warp-private rings, W resident, epilogue staging) plus:
//  - W-fragment register double-buffering (next gate's frags LDS'd during
//    current gate's MMAs -> W-LDS overlaps tensor issue)
//  - 3-stage A ring (prefetch distance 3, wait_group 2)
// Grid (16, 9) = 144 CTAs = one wave.

#define NG 7
#define HH 256
#define BK 32
#define NCHUNK 8
#define THREADS 384
#define GYS 9
#define STREAMS (12 * GYS)                  // 108 warp-streams per o-block

#define OFF_BIAS 0                          // 112 floats + pad = 512B
#define OFF_W 512
#define W_BYTES (NG * NCHUNK * 2 * 512)     // 112 frag-units x 512B = 57344
#define A_P_B 80                            // A stage row stride (bytes)
#define A_STAGE_B (32 * A_P_B)              // 2560
#define NSTAGE 3
#define A_WARP_B (NSTAGE * A_STAGE_B)       // 7680
#define OFF_A (OFF_W + W_BYTES)             // 57856
#define C_STRIDE_F 20                       // 80B row stride (16B-aligned)
#define C_ARR_B (32 * C_STRIDE_F * 4)       // 2560
#define C_WARP_B (2 * C_ARR_B + 128)        // c, cbar, dt = 5248
#define OFF_C (OFF_A + 12 * A_WARP_B)       // 150016
#define SMEM_BYTES (OFF_C + 12 * C_WARP_B)  // 212992

// fp16 copy of h_ti (B x H = 16.78M halfs = 32MB scratch)
__device__ __align__(16) __half2 g_h16[(65536 * 256) / 2];

__device__ __forceinline__ uint32_t pack_h2(float a, float b) {
    __half2 h = __floats2half2_rn(a, b);
    return *reinterpret_cast<uint32_t*>(&h);
}

__device__ __forceinline__ void mma_f16(float* d, const uint32_t* a,
                                        uint32_t b0, uint32_t b1) {
    asm volatile(
        "mma.sync.aligned.m16n8k16.row.col.f32.f16.f16.f32 "
        "{%0,%1,%2,%3}, {%4,%5,%6,%7}, {%8,%9}, {%0,%1,%2,%3};\n"
        : "+f"(d[0]), "+f"(d[1]), "+f"(d[2]), "+f"(d[3])
        : "r"(a[0]), "r"(a[1]), "r"(a[2]), "r"(a[3]), "r"(b0), "r"(b1));
}

__device__ __forceinline__ void cp_async16(uint32_t dst, const void* src) {
    asm volatile("cp.async.cg.shared.global [%0], [%1], 16;\n"
                 :: "r"(dst), "l"(src) : "memory");
}

__device__ __forceinline__ float tanh_fast(float x) {
    float y;
    asm("tanh.approx.f32 %0, %1;" : "=f"(y) : "f"(x));
    return y;
}
__device__ __forceinline__ float sigm(float x) {       // 0.5*tanh(x/2)+0.5
    return fmaf(tanh_fast(0.5f * x), 0.5f, 0.5f);
}

// ---- pre-pass: h_ti fp32 -> fp16 scratch (8 elems/thread) ----
extern "C" __global__ void __launch_bounds__(256, 1)
nctlstm_cvt_kernel(const float* __restrict__ src, int n8)
{
    const int i = blockIdx.x * 256 + threadIdx.x;
    if (i < n8) {
        const float4 f0 = reinterpret_cast<const float4*>(src)[2 * i];
        const float4 f1 = reinterpret_cast<const float4*>(src)[2 * i + 1];
        g_h16[4 * i + 0] = __floats2half2_rn(f0.x, f0.y);
        g_h16[4 * i + 1] = __floats2half2_rn(f0.z, f0.w);
        g_h16[4 * i + 2] = __floats2half2_rn(f1.x, f1.y);
        g_h16[4 * i + 3] = __floats2half2_rn(f1.z, f1.w);
    }
}

extern "C" __global__ void __launch_bounds__(THREADS, 1)
nctlstm_v14_kernel(const float* __restrict__ inter_times,
                   const float* __restrict__ c_ti,
                   const float* __restrict__ cbar,
                   const float* __restrict__ W,
                   const float* __restrict__ bias,
                   float* __restrict__ out,
                   int Btot)
{
    extern __shared__ char smem[];
    const uint32_t sb = (uint32_t)__cvta_generic_to_shared(smem);

    const int tid  = threadIdx.x;
    const int warp = tid >> 5;       // 0..11
    const int lane = tid & 31;
    const int grp  = lane >> 2;      // 0..7
    const int tig  = lane & 3;       // 0..3

    const int o0 = blockIdx.x * 16;
    const int stream = blockIdx.y * 12 + warp;   // 0..107
    const int nblk = Btot >> 5;                  // 2048 32-row blocks

    const __half* h16 = reinterpret_cast<const __half*>(g_h16);

    const float* bias_s = reinterpret_cast<const float*>(smem + OFF_BIAS);
    const uint4* wperm = reinterpret_cast<const uint4*>(smem + OFF_W);
    uint4* wperm_w = reinterpret_cast<uint4*>(smem + OFF_W);
    const uint32_t warpA = sb + OFF_A + (uint32_t)warp * A_WARP_B;
    const char*   warpAc = smem + OFF_A + warp * A_WARP_B;
    const uint32_t warpC = sb + OFF_C + (uint32_t)warp * C_WARP_B;
    const float*  c_s  = reinterpret_cast<const float*>(smem + OFF_C + warp * C_WARP_B);
    const float*  cb_s = c_s + (C_ARR_B / 4);
    const float*  dt_s = cb_s + (C_ARR_B / 4);

    // ---- warp-private A chunk loader: 32 rows x 32 halfs, 4 cp.async/lane --
    auto load_chunk = [&](int rb, int ch, int s) {
        const uint32_t ab = warpA + (uint32_t)s * A_STAGE_B;
        const __half* src = h16 + ((size_t)rb << 5) * HH + ch * BK;
#pragma unroll
        for (int i = 0; i < 4; i++) {
            const int idx = lane + i * 32;        // 0..127
            const int r = idx >> 2, g16 = idx & 3;
            cp_async16(ab + (uint32_t)(r * A_P_B + g16 * 16),
                       src + (size_t)r * HH + g16 * 8);
        }
        asm volatile("cp.async.commit_group;\n" ::: "memory");
    };

    // ---- epilogue-operand stager (NO commit; joins caller's group) ----
    auto load_cblock = [&](int rb) {
        const float* csrc  = c_ti + ((size_t)rb << 5) * HH + o0;
        const float* cbsrc = cbar + ((size_t)rb << 5) * HH + o0;
#pragma unroll
        for (int i = 0; i < 4; i++) {
            const int idx = lane + i * 32;        // 0..127
            const int r = idx >> 2, cg = idx & 3;
            cp_async16(warpC + (uint32_t)(r * (C_STRIDE_F * 4) + cg * 16),
                       csrc + (size_t)r * HH + cg * 4);
            cp_async16(warpC + (uint32_t)(C_ARR_B + r * (C_STRIDE_F * 4) + cg * 16),
                       cbsrc + (size_t)r * HH + cg * 4);
        }
        if (lane < 8)
            cp_async16(warpC + (uint32_t)(2 * C_ARR_B + lane * 16),
                       inter_times + (rb << 5) + lane * 4);
    };

    // prologue: first three chunks of first block in flight during W permute
    const int rb0 = stream;
    load_chunk(rb0, 0, 0);
    load_chunk(rb0, 1, 1);
    load_chunk(rb0, 2, 2);

    // ---- one-time W permute to fp16 k16-frag order (112 units) ----
    for (int u = warp; u < NG * NCHUNK * 2; u += 12) {
        const int nh = u & 1, ch = (u >> 1) & 7, g = u >> 4;
        const int o = o0 + nh * 8 + grp;
        const float* ws = W + ((size_t)g * HH + o) * HH + ch * 32 + 2 * tig;
        uint4 v;
        v.x = pack_h2(ws[0],  ws[1]);
        v.y = pack_h2(ws[8],  ws[9]);
        v.z = pack_h2(ws[16], ws[17]);
        v.w = pack_h2(ws[24], ws[25]);
        wperm_w[u * 32 + lane] = v;
    }

    // bias -> smem (112 floats, fp32)
    if (tid < NG * 16) {
        float* bw = reinterpret_cast<float*>(smem + OFF_BIAS);
        bw[tid] = bias[(size_t)(tid >> 4) * HH + o0 + (tid & 15)];
    }

    __syncthreads();   // W permute + bias visible; only block barrier

    const size_t BHtot = (size_t)Btot * HH;
    int s_cons = 0;

    for (int rb = rb0; rb < nblk; rb += STREAMS) {
        float acc[NG][2][2][4];          // [g][nh][mt][frag]
#pragma unroll
        for (int g = 0; g < NG; g++)
#pragma unroll
            for (int nh = 0; nh < 2; nh++) {
                const float2 bb = *reinterpret_cast<const float2*>(
                    bias_s + g * 16 + nh * 8 + 2 * tig);
#pragma unroll
                for (int mt = 0; mt < 2; mt++) {
                    acc[g][nh][mt][0] = bb.x; acc[g][nh][mt][1] = bb.y;
                    acc[g][nh][mt][2] = bb.x; acc[g][nh][mt][3] = bb.y;
                }
            }

#pragma unroll 1
        for (int ch = 0; ch < NCHUNK; ch++) {
            asm volatile("cp.async.wait_group 2;\n" ::: "memory");

            const char* hs = warpAc + s_cons * A_STAGE_B;

            // A fragments for both k16-steps (16 regs)
            uint32_t a[2][2][4];         // [ks][mt][frag]
#pragma unroll
            for (int ks = 0; ks < 2; ks++) {
#pragma unroll
                for (int mt = 0; mt < 2; mt++) {
                    const int r = mt * 16 + grp;
                    const char* rp0 = hs + r * A_P_B + ks * 32 + tig * 4;
                    const char* rp1 = hs + (r + 8) * A_P_B + ks * 32 + tig * 4;
                    a[ks][mt][0] = *reinterpret_cast<const uint32_t*>(rp0);
                    a[ks][mt][1] = *reinterpret_cast<const uint32_t*>(rp1);
                    a[ks][mt][2] = *reinterpret_cast<const uint32_t*>(rp0 + 16);
                    a[ks][mt][3] = *reinterpret_cast<const uint32_t*>(rp1 + 16);
                }
            }

            // all LDS from stage s_cons issued: safe to overwrite it.
            // chunk 0 also stages this block's epilogue operands (same group).
            {
                if (ch == 0) load_cblock(rb);
                int c2 = ch + NSTAGE, r2 = rb;
                if (c2 >= NCHUNK) { c2 -= NCHUNK; r2 += STREAMS; }
                if (r2 < nblk) load_chunk(r2, c2, s_cons);
                else           asm volatile("cp.async.commit_group;\n" ::: "memory");
            }
            s_cons += 1; if (s_cons == NSTAGE) s_cons = 0;

            // W-frag register double-buffer: load gate g+1's frags during
            // gate g's 8 MMAs (LDS->use distance ~64 tensor-cyc).
            const uint4* wch = wperm + (size_t)ch * 2 * 32 + lane;
            uint4 wf0 = wch[0];
            uint4 wf1 = wch[32];
#pragma unroll
            for (int g = 0; g < NG; g++) {
                uint4 nf0, nf1;
                if (g < NG - 1) {
                    nf0 = wch[(size_t)(g + 1) * 16 * 32];
                    nf1 = wch[(size_t)(g + 1) * 16 * 32 + 32];
                }
                mma_f16(acc[g][0][0], a[0][0], wf0.x, wf0.y);
                mma_f16(acc[g][0][1], a[0][1], wf0.x, wf0.y);
                mma_f16(acc[g][0][0], a[1][0], wf0.z, wf0.w);
                mma_f16(acc[g][0][1], a[1][1], wf0.z, wf0.w);
                mma_f16(acc[g][1][0], a[0][0], wf1.x, wf1.y);
                mma_f16(acc[g][1][1], a[0][1], wf1.x, wf1.y);
                mma_f16(acc[g][1][0], a[1][0], wf1.z, wf1.w);
                mma_f16(acc[g][1][1], a[1][1], wf1.z, wf1.w);
                wf0 = nf0;
                wf1 = nf1;
            }
        }

        // ---- fused epilogue: all operands in smem (staged in chunk 0) ----
#pragma unroll
        for (int mt = 0; mt < 2; mt++) {
#pragma unroll
            for (int rs = 0; rs < 2; rs++) {
                const int row = mt * 16 + grp + rs * 8;       // 0..31
                const int b = rb * 32 + row;
                const float dt = dt_s[row];
#pragma unroll
                for (int nh = 0; nh < 2; nh++) {
                    const int col = nh * 8 + 2 * tig;
                    const float2 cv = *reinterpret_cast<const float2*>(
                        c_s + row * C_STRIDE_F + col);
                    const float2 cb = *reinterpret_cast<const float2*>(
                        cb_s + row * C_STRIDE_F + col);
                    const size_t base = (size_t)b * HH + o0 + col;

                    float2 r_o, r_h, r_c, r_cb, r_d;
#pragma unroll
                    for (int j = 0; j < 2; j++) {
                        const int ai = rs * 2 + j;
                        const float gi  = acc[0][nh][mt][ai];
                        const float gf  = acc[1][nh][mt][ai];
                        const float go  = acc[2][nh][mt][ai];
                        const float gib = acc[3][nh][mt][ai];
                        const float gfb = acc[4][nh][mt][ai];
                        const float gz  = acc[5][nh][mt][ai];
                        const float gd  = acc[6][nh][mt][ai];

                        const float i_g  = sigm(gi);
                        const float f_g  = sigm(gf);
                        const float o_g  = sigm(go);
                        const float ib_g = sigm(gib);
                        const float fb_g = sigm(gfb);
                        const float z    = tanh_fast(gz);
                        const float decay = fmaxf(gd, 0.0f)
                                          + __logf(1.0f + __expf(-fabsf(gd)));

                        const float ct  = (j == 0) ? cv.x : cv.y;
                        const float cbv = (j == 0) ? cb.x : cb.y;

                        const float e       = __expf(-decay * dt);
                        const float c_after = cbv + (ct - cbv) * e;
                        const float c_new   = f_g * c_after + i_g * z;
                        const float cb_new  = fb_g * cbv + ib_g * z;
                        const float h_new   = o_g * tanh_fast(c_after);

                        if (j == 0) { r_o.x = o_g; r_h.x = h_new; r_c.x = c_new; r_cb.x = cb_new; r_d.x = decay; }
                        else        { r_o.y = o_g; r_h.y = h_new; r_c.y = c_new; r_cb.y = cb_new; r_d.y = decay; }
                    }
                    __stcs(reinterpret_cast<float2*>(out + 0 * BHtot + base), r_o);
                    __stcs(reinterpret_cast<float2*>(out + 1 * BHtot + base), r_h);
                    __stcs(reinterpret_cast<float2*>(out + 2 * BHtot + base), r_c);
                    __stcs(reinterpret_cast<float2*>(out + 3 * BHtot + base), r_cb);
                    __stcs(reinterpret_cast<float2*>(out + 4 * BHtot + base), r_d);
                }
            }
        }
    }
}

extern "C" void kernel_launch(void* const* d_in, const int* in_sizes, int n_in,
                              void* d_out, int out_size)
{
    const float* inter_times = (const float*)d_in[0];
    const float* h_ti        = (const float*)d_in[1];
    const float* c_ti        = (const float*)d_in[2];
    const float* cbar        = (const float*)d_in[3];
    const float* W           = (const float*)d_in[4];
    const float* bias        = (const float*)d_in[5];
    const int B = in_sizes[0];

    // pre-pass: h_ti -> fp16 scratch
    const int n8 = (B * HH) / 8;
    nctlstm_cvt_kernel<<<(n8 + 255) / 256, 256>>>(h_ti, n8);

    cudaFuncSetAttribute(nctlstm_v14_kernel,
                         cudaFuncAttributeMaxDynamicSharedMemorySize, SMEM_BYTES);

    dim3 grid(16, GYS);   // 144 CTAs = one wave; one 16-col o-block per CTA
    nctlstm_v14_kernel<<<grid, THREADS, SMEM_BYTES>>>(
        inter_times, c_ti, cbar, W, bias, (float*)d_out, B);
}